// round 14
// baseline (speedup 1.0000x reference)
#include <cuda_runtime.h>
#include <math.h>
#include <stdint.h>

#define D_MODEL 1024
#define NHEAD   16
#define DHEAD   64
#define BB      2
#define TT      2048
#define SSEQ    2048
#define MROWS   (BB*TT)      // 4096
#define DFF_    4096

// ---------------- scratch (device globals; no runtime allocation) ----------------
__device__ float g_q  [MROWS * D_MODEL];
__device__ float g_k  [MROWS * D_MODEL];
__device__ float g_v  [MROWS * D_MODEL];
__device__ float g_ctx[MROWS * D_MODEL];
__device__ float g_tmp[MROWS * D_MODEL];
__device__ float g_x1 [MROWS * D_MODEL];
__device__ float g_x2 [MROWS * D_MODEL];
__device__ float g_ffh[(size_t)MROWS * DFF_];

__device__ __forceinline__ void mma_tf32(
    float* c, uint32_t a0, uint32_t a1, uint32_t a2, uint32_t a3,
    uint32_t b0, uint32_t b1)
{
    asm volatile(
        "mma.sync.aligned.m16n8k8.row.col.f32.tf32.tf32.f32 "
        "{%0,%1,%2,%3}, {%4,%5,%6,%7}, {%8,%9}, {%0,%1,%2,%3};"
        : "+f"(c[0]), "+f"(c[1]), "+f"(c[2]), "+f"(c[3])
        : "r"(a0), "r"(a1), "r"(a2), "r"(a3), "r"(b0), "r"(b1));
}

__device__ __forceinline__ void cp16(void* smem_ptr, const void* gptr) {
    uint32_t sa = (uint32_t)__cvta_generic_to_shared(smem_ptr);
    asm volatile("cp.async.cg.shared.global [%0], [%1], 16;" :: "r"(sa), "l"(gptr));
}
#define CP_COMMIT() asm volatile("cp.async.commit_group;")
#define CP_WAIT(n)  asm volatile("cp.async.wait_group %0;" :: "n"(n))

__device__ __forceinline__ float fast_exp2(float x) {
    float r;
    asm("ex2.approx.f32 %0, %1;" : "=f"(r) : "f"(x));
    return r;
}

#define AST 20
#define NSTAGE 4

// ================= 128x128 TF32 GEMM (cp.async 4-stage, 2 CTAs/SM) ==========
__device__ __forceinline__ void gemm_body(
    const float* __restrict__ A, const float* __restrict__ B,
    const float* __restrict__ bias, const float* __restrict__ resid,
    float* __restrict__ C, int N, int K, int do_relu, int bm, int bn)
{
    __shared__ float As[NSTAGE][128 * AST];
    __shared__ float Bs[NSTAGE][128 * AST];

    const int tid  = threadIdx.x;
    const int warp = tid >> 5;
    const int lane = tid & 31;
    const int g    = lane >> 2;
    const int tg   = lane & 3;
    const int warp_m = (warp & 1) * 64;
    const int warp_n = (warp >> 1) * 32;

    const int r0 = tid >> 2;
    const int c4 = tid & 3;
    const float* Ar0 = A + (size_t)(bm + r0)      * K + c4 * 4;
    const float* Ar1 = A + (size_t)(bm + r0 + 64) * K + c4 * 4;
    const float* Br0 = B + (size_t)(bn + r0)      * K + c4 * 4;
    const float* Br1 = B + (size_t)(bn + r0 + 64) * K + c4 * 4;
    const int soff = r0 * AST + c4 * 4;

    float acc[4][4][4];
#pragma unroll
    for (int i = 0; i < 4; i++)
#pragma unroll
        for (int j = 0; j < 4; j++)
#pragma unroll
            for (int c = 0; c < 4; c++) acc[i][j][c] = 0.f;

    const int nk = K >> 4;

#pragma unroll
    for (int s = 0; s < NSTAGE - 1; s++) {
        const int k0 = s << 4;
        cp16(&As[s][soff],            Ar0 + k0);
        cp16(&As[s][soff + 64 * AST], Ar1 + k0);
        cp16(&Bs[s][soff],            Br0 + k0);
        cp16(&Bs[s][soff + 64 * AST], Br1 + k0);
        CP_COMMIT();
    }

    for (int kt = 0; kt < nk; kt++) {
        CP_WAIT(NSTAGE - 2);
        __syncthreads();

        if (kt + NSTAGE - 1 < nk) {
            const int buf = (kt + NSTAGE - 1) & (NSTAGE - 1);
            const int k0 = (kt + NSTAGE - 1) << 4;
            cp16(&As[buf][soff],            Ar0 + k0);
            cp16(&As[buf][soff + 64 * AST], Ar1 + k0);
            cp16(&Bs[buf][soff],            Br0 + k0);
            cp16(&Bs[buf][soff + 64 * AST], Br1 + k0);
        }
        CP_COMMIT();

        const uint32_t* Ab = (const uint32_t*)As[kt & (NSTAGE - 1)];
        const uint32_t* Bb = (const uint32_t*)Bs[kt & (NSTAGE - 1)];
#pragma unroll
        for (int ks = 0; ks < 2; ks++) {
            const int k0 = ks * 8;
            uint32_t af[4][4], bf[4][2];
#pragma unroll
            for (int i = 0; i < 4; i++) {
                const int row = warp_m + i * 16 + g;
                af[i][0] = Ab[row * AST + k0 + tg];
                af[i][1] = Ab[(row + 8) * AST + k0 + tg];
                af[i][2] = Ab[row * AST + k0 + tg + 4];
                af[i][3] = Ab[(row + 8) * AST + k0 + tg + 4];
            }
#pragma unroll
            for (int j = 0; j < 4; j++) {
                const int col = warp_n + j * 8 + g;
                bf[j][0] = Bb[col * AST + k0 + tg];
                bf[j][1] = Bb[col * AST + k0 + tg + 4];
            }
#pragma unroll
            for (int i = 0; i < 4; i++)
#pragma unroll
                for (int j = 0; j < 4; j++)
                    mma_tf32(acc[i][j], af[i][0], af[i][1], af[i][2], af[i][3],
                             bf[j][0], bf[j][1]);
        }
        // no trailing barrier: next iteration's wait_group+syncthreads protects reuse
    }

#pragma unroll
    for (int j = 0; j < 4; j++) {
        const int col = bn + warp_n + j * 8 + tg * 2;
        const float bx = bias[col], by = bias[col + 1];
#pragma unroll
        for (int i = 0; i < 4; i++) {
            const int row0 = bm + warp_m + i * 16 + g;
            const int row1 = row0 + 8;
            float o00 = acc[i][j][0] + bx, o01 = acc[i][j][1] + by;
            float o10 = acc[i][j][2] + bx, o11 = acc[i][j][3] + by;
            if (do_relu) {
                o00 = fmaxf(o00, 0.f); o01 = fmaxf(o01, 0.f);
                o10 = fmaxf(o10, 0.f); o11 = fmaxf(o11, 0.f);
            }
            if (resid) {
                const float2 r0v = *(const float2*)(resid + (size_t)row0 * N + col);
                const float2 r1v = *(const float2*)(resid + (size_t)row1 * N + col);
                o00 += r0v.x; o01 += r0v.y; o10 += r1v.x; o11 += r1v.y;
            }
            *(float2*)(C + (size_t)row0 * N + col) = make_float2(o00, o01);
            *(float2*)(C + (size_t)row1 * N + col) = make_float2(o10, o11);
        }
    }
}

__global__ __launch_bounds__(256, 2) void gemm_tf32(
    const float* __restrict__ A, const float* __restrict__ B,
    const float* __restrict__ bias, const float* __restrict__ resid,
    float* __restrict__ C, int N, int K, int do_relu)
{
    gemm_body(A, B, bias, resid, C, N, K, do_relu,
              blockIdx.y * 128, blockIdx.x * 128);
}

__global__ __launch_bounds__(256, 2) void gemm_tf32_multi(
    const float* __restrict__ A,
    const float* __restrict__ W0, const float* __restrict__ W1, const float* __restrict__ W2,
    const float* __restrict__ b0, const float* __restrict__ b1, const float* __restrict__ b2,
    float* __restrict__ C0, float* __restrict__ C1, float* __restrict__ C2)
{
    const int wsel = blockIdx.x >> 3;
    const int bn = (blockIdx.x & 7) * 128;
    const float* B    = (wsel == 0) ? W0 : (wsel == 1) ? W1 : W2;
    const float* bias = (wsel == 0) ? b0 : (wsel == 1) ? b1 : b2;
    float* C          = (wsel == 0) ? C0 : (wsel == 1) ? C1 : C2;
    gemm_body(A, B, bias, nullptr, C, D_MODEL, D_MODEL, 0,
              blockIdx.y * 128, bn);
}

// ================= 256x128 TF32 GEMM (one-wave variant for N=1024 GEMMs) ======
__global__ __launch_bounds__(256, 1) void gemm_tf32_big(
    const float* __restrict__ A, const float* __restrict__ B,
    const float* __restrict__ bias, const float* __restrict__ resid,
    float* __restrict__ C, int N, int K, int do_relu)
{
    __shared__ float As[NSTAGE][256 * AST];
    __shared__ float Bs[NSTAGE][128 * AST];

    const int tid  = threadIdx.x;
    const int warp = tid >> 5;
    const int lane = tid & 31;
    const int g    = lane >> 2;
    const int tg   = lane & 3;
    const int warp_m = (warp & 3) * 64;
    const int warp_n = (warp >> 2) * 64;
    const int bm = blockIdx.y * 256;
    const int bn = blockIdx.x * 128;

    const int r0 = tid >> 2;
    const int c4 = tid & 3;
    const float* Ar0 = A + (size_t)(bm + r0)       * K + c4 * 4;
    const float* Ar1 = A + (size_t)(bm + r0 + 64)  * K + c4 * 4;
    const float* Ar2 = A + (size_t)(bm + r0 + 128) * K + c4 * 4;
    const float* Ar3 = A + (size_t)(bm + r0 + 192) * K + c4 * 4;
    const float* Br0 = B + (size_t)(bn + r0)       * K + c4 * 4;
    const float* Br1 = B + (size_t)(bn + r0 + 64)  * K + c4 * 4;
    const int soff = r0 * AST + c4 * 4;

    float acc[4][8][4];
#pragma unroll
    for (int i = 0; i < 4; i++)
#pragma unroll
        for (int j = 0; j < 8; j++)
#pragma unroll
            for (int c = 0; c < 4; c++) acc[i][j][c] = 0.f;

    const int nk = K >> 4;

#pragma unroll
    for (int s = 0; s < NSTAGE - 1; s++) {
        const int k0 = s << 4;
        cp16(&As[s][soff],             Ar0 + k0);
        cp16(&As[s][soff + 64 * AST],  Ar1 + k0);
        cp16(&As[s][soff + 128 * AST], Ar2 + k0);
        cp16(&As[s][soff + 192 * AST], Ar3 + k0);
        cp16(&Bs[s][soff],             Br0 + k0);
        cp16(&Bs[s][soff + 64 * AST],  Br1 + k0);
        CP_COMMIT();
    }

    for (int kt = 0; kt < nk; kt++) {
        CP_WAIT(NSTAGE - 2);
        __syncthreads();

        if (kt + NSTAGE - 1 < nk) {
            const int buf = (kt + NSTAGE - 1) & (NSTAGE - 1);
            const int k0 = (kt + NSTAGE - 1) << 4;
            cp16(&As[buf][soff],             Ar0 + k0);
            cp16(&As[buf][soff + 64 * AST],  Ar1 + k0);
            cp16(&As[buf][soff + 128 * AST], Ar2 + k0);
            cp16(&As[buf][soff + 192 * AST], Ar3 + k0);
            cp16(&Bs[buf][soff],             Br0 + k0);
            cp16(&Bs[buf][soff + 64 * AST],  Br1 + k0);
        }
        CP_COMMIT();

        const uint32_t* Ab = (const uint32_t*)As[kt & (NSTAGE - 1)];
        const uint32_t* Bb = (const uint32_t*)Bs[kt & (NSTAGE - 1)];
#pragma unroll
        for (int ks = 0; ks < 2; ks++) {
            const int k0 = ks * 8;
            uint32_t af[4][4], bf[8][2];
#pragma unroll
            for (int i = 0; i < 4; i++) {
                const int row = warp_m + i * 16 + g;
                af[i][0] = Ab[row * AST + k0 + tg];
                af[i][1] = Ab[(row + 8) * AST + k0 + tg];
                af[i][2] = Ab[row * AST + k0 + tg + 4];
                af[i][3] = Ab[(row + 8) * AST + k0 + tg + 4];
            }
#pragma unroll
            for (int j = 0; j < 8; j++) {
                const int col = warp_n + j * 8 + g;
                bf[j][0] = Bb[col * AST + k0 + tg];
                bf[j][1] = Bb[col * AST + k0 + tg + 4];
            }
#pragma unroll
            for (int i = 0; i < 4; i++)
#pragma unroll
                for (int j = 0; j < 8; j++)
                    mma_tf32(acc[i][j], af[i][0], af[i][1], af[i][2], af[i][3],
                             bf[j][0], bf[j][1]);
        }
        // no trailing barrier (see gemm_body)
    }

#pragma unroll
    for (int j = 0; j < 8; j++) {
        const int col = bn + warp_n + j * 8 + tg * 2;
        const float bx = bias[col], by = bias[col + 1];
#pragma unroll
        for (int i = 0; i < 4; i++) {
            const int row0 = bm + warp_m + i * 16 + g;
            const int row1 = row0 + 8;
            float o00 = acc[i][j][0] + bx, o01 = acc[i][j][1] + by;
            float o10 = acc[i][j][2] + bx, o11 = acc[i][j][3] + by;
            if (do_relu) {
                o00 = fmaxf(o00, 0.f); o01 = fmaxf(o01, 0.f);
                o10 = fmaxf(o10, 0.f); o11 = fmaxf(o11, 0.f);
            }
            if (resid) {
                const float2 r0v = *(const float2*)(resid + (size_t)row0 * N + col);
                const float2 r1v = *(const float2*)(resid + (size_t)row1 * N + col);
                o00 += r0v.x; o01 += r0v.y; o10 += r1v.x; o11 += r1v.y;
            }
            *(float2*)(C + (size_t)row0 * N + col) = make_float2(o00, o01);
            *(float2*)(C + (size_t)row1 * N + col) = make_float2(o10, o11);
        }
    }
}

// ===== Flash attention, Br=128 x Bc=64, 256 thr, cp.async 2-stage K/V,
//       shuffle-based P conversion, exp2-domain softmax -> 2 CTAs/SM
#define QST 68   // 68 % 32 == 4 -> conflict-free a-frag loads
#define VST 72   // 72 % 32 == 8 -> conflict-free V b-frag loads
#define KSTAGE_U32 (64 * QST)
#define VSTAGE_U32 (64 * VST)
// layout: Qs[128*QST] | Ks[2][64*QST] | Vs[2][64*VST]
#define FA5_SMEM_U32 (128*QST + 2*KSTAGE_U32 + 2*VSTAGE_U32)
#define FA5_SMEM_BYTES (FA5_SMEM_U32 * 4)
#define QSCALE (0.125f * 1.4426950408889634f)   // 1/sqrt(64) * log2(e)

__global__ __launch_bounds__(256, 2) void flash_attn_mma(
    const float* __restrict__ Q, const float* __restrict__ Kg,
    const float* __restrict__ Vg, float* __restrict__ O,
    int Tq, int Tk, int causal)
{
    extern __shared__ uint32_t smu[];
    uint32_t* Qs = smu;
    uint32_t* Ks = smu + 128 * QST;
    uint32_t* Vs = Ks + 2 * KSTAGE_U32;

    const int tid  = threadIdx.x;
    const int w    = tid >> 5;
    const int lane = tid & 31;
    const int g    = lane >> 2;
    const int tg   = lane & 3;
    const int m0   = w * 16;
    const int qtile = causal ? ((int)gridDim.x - 1 - (int)blockIdx.x) : (int)blockIdx.x;
    const int qb   = qtile * 128;
    const int h    = blockIdx.y;
    const int bb   = blockIdx.z;

    // shuffle sources for accumulator->A-frag conversion (within the 4-lane quad)
    const int srcA = (lane & 28) | (tg >> 1);
    const int srcB = srcA + 2;
    const bool odd = (tg & 1) != 0;

    const float* Qbase = Q  + (size_t)bb * Tq * D_MODEL + h * DHEAD;
    const float* Kbase = Kg + (size_t)bb * Tk * D_MODEL + h * DHEAD;
    const float* Vbase = Vg + (size_t)bb * Tk * D_MODEL + h * DHEAD;

    const int ntiles = causal ? (2 * (qtile + 1)) : (Tk >> 6);

    // prologue: async-load K/V tile 0 into stage 0
    {
#pragma unroll
        for (int i = 0; i < 4; i++) {
            const int f = tid + i * 256;
            const int r = f >> 4, d4 = f & 15;
            cp16(&Ks[r * QST + d4 * 4], Kbase + (size_t)r * D_MODEL + d4 * 4);
            cp16(&Vs[r * VST + d4 * 4], Vbase + (size_t)r * D_MODEL + d4 * 4);
        }
        CP_COMMIT();
    }

    // load Q tile (128 rows), pre-scaled into exp2 domain
#pragma unroll
    for (int i = 0; i < 8; i++) {
        const int f = tid + i * 256;
        const int r = f >> 4, d4 = f & 15;
        float4 v = *(const float4*)(Qbase + (size_t)(qb + r) * D_MODEL + d4 * 4);
        uint4 u = make_uint4(__float_as_uint(v.x * QSCALE), __float_as_uint(v.y * QSCALE),
                             __float_as_uint(v.z * QSCALE), __float_as_uint(v.w * QSCALE));
        *(uint4*)&Qs[r * QST + d4 * 4] = u;
    }

    float o[8][4];
#pragma unroll
    for (int nt = 0; nt < 8; nt++)
#pragma unroll
        for (int c = 0; c < 4; c++) o[nt][c] = 0.f;
    float mrow0 = -INFINITY, mrow1 = -INFINITY;
    float lrow0 = 0.f, lrow1 = 0.f;

    for (int t = 0; t < ntiles; t++) {
        // prefetch tile t+1 into the other stage
        if (t + 1 < ntiles) {
            const int kb1 = (t + 1) * 64;
            uint32_t* Kn = Ks + ((t + 1) & 1) * KSTAGE_U32;
            uint32_t* Vn = Vs + ((t + 1) & 1) * VSTAGE_U32;
#pragma unroll
            for (int i = 0; i < 4; i++) {
                const int f = tid + i * 256;
                const int r = f >> 4, d4 = f & 15;
                cp16(&Kn[r * QST + d4 * 4], Kbase + (size_t)(kb1 + r) * D_MODEL + d4 * 4);
                cp16(&Vn[r * VST + d4 * 4], Vbase + (size_t)(kb1 + r) * D_MODEL + d4 * 4);
            }
        }
        CP_COMMIT();
        CP_WAIT(1);
        __syncthreads();

        const uint32_t* Kb = Ks + (t & 1) * KSTAGE_U32;
        const uint32_t* Vb = Vs + (t & 1) * VSTAGE_U32;
        const int kb = t * 64;

        // ---- S = Q @ K^T (16x64 per warp), S in log2-units ----
        float s[8][4];
#pragma unroll
        for (int nt = 0; nt < 8; nt++)
#pragma unroll
            for (int c = 0; c < 4; c++) s[nt][c] = 0.f;
#pragma unroll
        for (int kk = 0; kk < 8; kk++) {
            const int k0 = kk * 8;
            const uint32_t a0 = Qs[(m0 + g)     * QST + k0 + tg];
            const uint32_t a1 = Qs[(m0 + g + 8) * QST + k0 + tg];
            const uint32_t a2 = Qs[(m0 + g)     * QST + k0 + tg + 4];
            const uint32_t a3 = Qs[(m0 + g + 8) * QST + k0 + tg + 4];
#pragma unroll
            for (int nt = 0; nt < 8; nt++) {
                const uint32_t b0 = Kb[(nt * 8 + g) * QST + k0 + tg];
                const uint32_t b1 = Kb[(nt * 8 + g) * QST + k0 + tg + 4];
                mma_tf32(s[nt], a0, a1, a2, a3, b0, b1);
            }
        }

        if (causal && t >= 2 * qtile) {
            const int row0 = qb + m0 + g;
            const int row1 = row0 + 8;
#pragma unroll
            for (int nt = 0; nt < 8; nt++) {
                const int col = kb + nt * 8 + 2 * tg;
                if (col     > row0) s[nt][0] = -1e30f;
                if (col + 1 > row0) s[nt][1] = -1e30f;
                if (col     > row1) s[nt][2] = -1e30f;
                if (col + 1 > row1) s[nt][3] = -1e30f;
            }
        }

        // ---- online softmax in exp2 domain ----
        float ml0 = -INFINITY, ml1 = -INFINITY;
#pragma unroll
        for (int nt = 0; nt < 8; nt++) {
            ml0 = fmaxf(ml0, fmaxf(s[nt][0], s[nt][1]));
            ml1 = fmaxf(ml1, fmaxf(s[nt][2], s[nt][3]));
        }
        ml0 = fmaxf(ml0, __shfl_xor_sync(0xffffffffu, ml0, 1));
        ml0 = fmaxf(ml0, __shfl_xor_sync(0xffffffffu, ml0, 2));
        ml1 = fmaxf(ml1, __shfl_xor_sync(0xffffffffu, ml1, 1));
        ml1 = fmaxf(ml1, __shfl_xor_sync(0xffffffffu, ml1, 2));

        const float mn0 = fmaxf(mrow0, ml0);
        const float mn1 = fmaxf(mrow1, ml1);
        const float al0 = fast_exp2(mrow0 - mn0);
        const float al1 = fast_exp2(mrow1 - mn1);
        float ps0 = 0.f, ps1 = 0.f;
#pragma unroll
        for (int nt = 0; nt < 8; nt++) {
            s[nt][0] = fast_exp2(s[nt][0] - mn0);
            s[nt][1] = fast_exp2(s[nt][1] - mn0);
            s[nt][2] = fast_exp2(s[nt][2] - mn1);
            s[nt][3] = fast_exp2(s[nt][3] - mn1);
            ps0 += s[nt][0] + s[nt][1];
            ps1 += s[nt][2] + s[nt][3];
        }
        ps0 += __shfl_xor_sync(0xffffffffu, ps0, 1);
        ps0 += __shfl_xor_sync(0xffffffffu, ps0, 2);
        ps1 += __shfl_xor_sync(0xffffffffu, ps1, 1);
        ps1 += __shfl_xor_sync(0xffffffffu, ps1, 2);
        lrow0 = lrow0 * al0 + ps0;
        lrow1 = lrow1 * al1 + ps1;
        mrow0 = mn0;
        mrow1 = mn1;
#pragma unroll
        for (int nt = 0; nt < 8; nt++) {
            o[nt][0] *= al0; o[nt][1] *= al0;
            o[nt][2] *= al1; o[nt][3] *= al1;
        }

        // ---- O += P @ V : shuffle-convert accumulator frags -> A frags ----
#pragma unroll
        for (int kk = 0; kk < 8; kk++) {
            const float v0 = __shfl_sync(0xffffffffu, s[kk][0], srcA);
            const float v1 = __shfl_sync(0xffffffffu, s[kk][1], srcA);
            const float v2 = __shfl_sync(0xffffffffu, s[kk][2], srcA);
            const float v3 = __shfl_sync(0xffffffffu, s[kk][3], srcA);
            const float w0 = __shfl_sync(0xffffffffu, s[kk][0], srcB);
            const float w1 = __shfl_sync(0xffffffffu, s[kk][1], srcB);
            const float w2 = __shfl_sync(0xffffffffu, s[kk][2], srcB);
            const float w3 = __shfl_sync(0xffffffffu, s[kk][3], srcB);
            const uint32_t a0 = __float_as_uint(odd ? v1 : v0);
            const uint32_t a1 = __float_as_uint(odd ? v3 : v2);
            const uint32_t a2 = __float_as_uint(odd ? w1 : w0);
            const uint32_t a3 = __float_as_uint(odd ? w3 : w2);
            const int k0 = kk * 8;
#pragma unroll
            for (int nt = 0; nt < 8; nt++) {
                const uint32_t b0 = Vb[(k0 + tg)     * VST + nt * 8 + g];
                const uint32_t b1 = Vb[(k0 + tg + 4) * VST + nt * 8 + g];
                mma_tf32(o[nt], a0, a1, a2, a3, b0, b1);
            }
        }
        __syncthreads();   // all reads of stage (t&1) done before its reuse at t+2
    }

    const float inv0 = 1.f / lrow0;
    const float inv1 = 1.f / lrow1;
    const int row0 = qb + m0 + g;
    const int row1 = row0 + 8;
#pragma unroll
    for (int nt = 0; nt < 8; nt++) {
        const int col = h * DHEAD + nt * 8 + 2 * tg;
        *(float2*)(O + ((size_t)bb * Tq + row0) * D_MODEL + col) =
            make_float2(o[nt][0] * inv0, o[nt][1] * inv0);
        *(float2*)(O + ((size_t)bb * Tq + row1) * D_MODEL + col) =
            make_float2(o[nt][2] * inv1, o[nt][3] * inv1);
    }
}

// ---------------- LN over rows of 1024 ----------------
__global__ __launch_bounds__(256) void ln_kernel(
    const float* __restrict__ in, const float* __restrict__ g,
    const float* __restrict__ b, float* __restrict__ out)
{
    const int row = blockIdx.x;
    const int tid = threadIdx.x;
    float4 v = ((const float4*)(in + (size_t)row * D_MODEL))[tid];
    float s  = v.x + v.y + v.z + v.w;
    float ss = v.x*v.x + v.y*v.y + v.z*v.z + v.w*v.w;
#pragma unroll
    for (int off = 16; off > 0; off >>= 1) {
        s  += __shfl_xor_sync(0xffffffffu, s,  off);
        ss += __shfl_xor_sync(0xffffffffu, ss, off);
    }
    __shared__ float ws[8], wss[8];
    __shared__ float s_mu, s_inv;
    const int warp = tid >> 5, lane = tid & 31;
    if (lane == 0) { ws[warp] = s; wss[warp] = ss; }
    __syncthreads();
    if (tid == 0) {
        float ts = 0.f, tss = 0.f;
#pragma unroll
        for (int w = 0; w < 8; w++) { ts += ws[w]; tss += wss[w]; }
        float mu = ts * (1.f / D_MODEL);
        float var = tss * (1.f / D_MODEL) - mu * mu;
        s_mu = mu;
        s_inv = rsqrtf(var + 1e-5f);
    }
    __syncthreads();
    float mu = s_mu, inv = s_inv;
    float4 gg = ((const float4*)g)[tid];
    float4 bb = ((const float4*)b)[tid];
    float4 r;
    r.x = (v.x - mu) * inv * gg.x + bb.x;
    r.y = (v.y - mu) * inv * gg.y + bb.y;
    r.z = (v.z - mu) * inv * gg.z + bb.z;
    r.w = (v.w - mu) * inv * gg.w + bb.w;
    ((float4*)(out + (size_t)row * D_MODEL))[tid] = r;
}

// ---------------- orchestration ----------------
extern "C" void kernel_launch(void* const* d_in, const int* in_sizes, int n_in,
                              void* d_out, int out_size)
{
    const float* x     = (const float*)d_in[0];
    const float* enc   = (const float*)d_in[1];
    const float* sa_Wq = (const float*)d_in[4];
    const float* sa_bq = (const float*)d_in[5];
    const float* sa_Wk = (const float*)d_in[6];
    const float* sa_bk = (const float*)d_in[7];
    const float* sa_Wv = (const float*)d_in[8];
    const float* sa_bv = (const float*)d_in[9];
    const float* sa_Wo = (const float*)d_in[10];
    const float* sa_bo = (const float*)d_in[11];
    const float* ca_Wq = (const float*)d_in[12];
    const float* ca_bq = (const float*)d_in[13];
    const float* ca_Wk = (const float*)d_in[14];
    const float* ca_bk = (const float*)d_in[15];
    const float* ca_Wv = (const float*)d_in[16];
    const float* ca_bv = (const float*)d_in[17];
    const float* ca_Wo = (const float*)d_in[18];
    const float* ca_bo = (const float*)d_in[19];
    const float* ff_W1 = (const float*)d_in[20];
    const float* ff_b1 = (const float*)d_in[21];
    const float* ff_W2 = (const float*)d_in[22];
    const float* ff_b2 = (const float*)d_in[23];
    const float* ln1_g = (const float*)d_in[24];
    const float* ln1_b = (const float*)d_in[25];
    const float* ln2_g = (const float*)d_in[26];
    const float* ln2_b = (const float*)d_in[27];
    const float* ln3_g = (const float*)d_in[28];
    const float* ln3_b = (const float*)d_in[29];

    float *q, *k, *v, *ctx, *tmp, *x1, *x2, *ffh;
    cudaGetSymbolAddress((void**)&q,   g_q);
    cudaGetSymbolAddress((void**)&k,   g_k);
    cudaGetSymbolAddress((void**)&v,   g_v);
    cudaGetSymbolAddress((void**)&ctx, g_ctx);
    cudaGetSymbolAddress((void**)&tmp, g_tmp);
    cudaGetSymbolAddress((void**)&x1,  g_x1);
    cudaGetSymbolAddress((void**)&x2,  g_x2);
    cudaGetSymbolAddress((void**)&ffh, g_ffh);

    cudaFuncSetAttribute(flash_attn_mma, cudaFuncAttributeMaxDynamicSharedMemorySize, FA5_SMEM_BYTES);

    dim3 gqkv(24, MROWS/128);               // fused q,k,v projections (128-tile)
    dim3 gkv2(16, MROWS/128);               // fused cross k,v (128-tile)
    dim3 gbig(D_MODEL/128, MROWS/256);      // (8,16) = 128 blocks, one wave
    dim3 gf1(DFF_/128,  MROWS/128);         // FFN up
    dim3 gfa(TT/128, NHEAD, BB);            // flash attention (Br=128)

    // --- self attention ---
    gemm_tf32_multi<<<gqkv, 256>>>(x, sa_Wq, sa_Wk, sa_Wv, sa_bq, sa_bk, sa_bv, q, k, v);
    flash_attn_mma<<<gfa, 256, FA5_SMEM_BYTES>>>(q, k, v, ctx, TT, TT, 1);
    gemm_tf32_big<<<gbig, 256>>>(ctx, sa_Wo, sa_bo, x, tmp, D_MODEL, D_MODEL, 0);
    ln_kernel<<<MROWS, 256>>>(tmp, ln1_g, ln1_b, x1);

    // --- cross attention ---
    gemm_tf32_multi<<<gkv2, 256>>>(enc, ca_Wk, ca_Wv, nullptr, ca_bk, ca_bv, nullptr, k, v, nullptr);
    gemm_tf32_big<<<gbig, 256>>>(x1, ca_Wq, ca_bq, nullptr, q, D_MODEL, D_MODEL, 0);
    flash_attn_mma<<<gfa, 256, FA5_SMEM_BYTES>>>(q, k, v, ctx, TT, SSEQ, 0);
    gemm_tf32_big<<<gbig, 256>>>(ctx, ca_Wo, ca_bo, x1, tmp, D_MODEL, D_MODEL, 0);
    ln_kernel<<<MROWS, 256>>>(tmp, ln2_g, ln2_b, x2);

    // --- FFN ---
    gemm_tf32<<<gf1, 256>>>(x2,  ff_W1, ff_b1, nullptr, ffh, DFF_,    D_MODEL, 1);
    gemm_tf32_big<<<gbig, 256>>>(ffh, ff_W2, ff_b2, x2,  tmp, D_MODEL, DFF_,    0);
    ln_kernel<<<MROWS, 256>>>(tmp, ln3_g, ln3_b, (float*)d_out);
}

// round 15
// speedup vs baseline: 1.5542x; 1.5542x over previous
#include <cuda_runtime.h>
#include <math.h>
#include <stdint.h>

#define D_MODEL 1024
#define NHEAD   16
#define DHEAD   64
#define BB      2
#define TT      2048
#define SSEQ    2048
#define MROWS   (BB*TT)      // 4096
#define DFF_    4096

// ---------------- scratch (device globals; no runtime allocation) ----------------
__device__ float g_q  [MROWS * D_MODEL];
__device__ float g_k  [MROWS * D_MODEL];
__device__ float g_v  [MROWS * D_MODEL];
__device__ float g_ctx[MROWS * D_MODEL];
__device__ float g_tmp[MROWS * D_MODEL];
__device__ float g_x1 [MROWS * D_MODEL];
__device__ float g_x2 [MROWS * D_MODEL];
__device__ float g_ffh[(size_t)MROWS * DFF_];

__device__ __forceinline__ void mma_tf32(
    float* c, uint32_t a0, uint32_t a1, uint32_t a2, uint32_t a3,
    uint32_t b0, uint32_t b1)
{
    asm volatile(
        "mma.sync.aligned.m16n8k8.row.col.f32.tf32.tf32.f32 "
        "{%0,%1,%2,%3}, {%4,%5,%6,%7}, {%8,%9}, {%0,%1,%2,%3};"
        : "+f"(c[0]), "+f"(c[1]), "+f"(c[2]), "+f"(c[3])
        : "r"(a0), "r"(a1), "r"(a2), "r"(a3), "r"(b0), "r"(b1));
}

__device__ __forceinline__ void cp16(void* smem_ptr, const void* gptr) {
    uint32_t sa = (uint32_t)__cvta_generic_to_shared(smem_ptr);
    asm volatile("cp.async.cg.shared.global [%0], [%1], 16;" :: "r"(sa), "l"(gptr));
}
#define CP_COMMIT() asm volatile("cp.async.commit_group;")
#define CP_WAIT(n)  asm volatile("cp.async.wait_group %0;" :: "n"(n))

__device__ __forceinline__ float fast_exp2(float x) {
    float r;
    asm("ex2.approx.f32 %0, %1;" : "=f"(r) : "f"(x));
    return r;
}

#define AST 20
#define NSTAGE 4

// ================= 128x128 TF32 GEMM (cp.async 4-stage, single barrier/iter) ==
__device__ __forceinline__ void gemm_body(
    const float* __restrict__ A, const float* __restrict__ B,
    const float* __restrict__ bias, const float* __restrict__ resid,
    float* __restrict__ C, int N, int K, int do_relu, int bm, int bn)
{
    __shared__ float As[NSTAGE][128 * AST];
    __shared__ float Bs[NSTAGE][128 * AST];

    const int tid  = threadIdx.x;
    const int warp = tid >> 5;
    const int lane = tid & 31;
    const int g    = lane >> 2;
    const int tg   = lane & 3;
    const int warp_m = (warp & 1) * 64;
    const int warp_n = (warp >> 1) * 32;

    const int r0 = tid >> 2;
    const int c4 = tid & 3;
    const float* Ar0 = A + (size_t)(bm + r0)      * K + c4 * 4;
    const float* Ar1 = A + (size_t)(bm + r0 + 64) * K + c4 * 4;
    const float* Br0 = B + (size_t)(bn + r0)      * K + c4 * 4;
    const float* Br1 = B + (size_t)(bn + r0 + 64) * K + c4 * 4;
    const int soff = r0 * AST + c4 * 4;

    float acc[4][4][4];
#pragma unroll
    for (int i = 0; i < 4; i++)
#pragma unroll
        for (int j = 0; j < 4; j++)
#pragma unroll
            for (int c = 0; c < 4; c++) acc[i][j][c] = 0.f;

    const int nk = K >> 4;

#pragma unroll
    for (int s = 0; s < NSTAGE - 1; s++) {
        const int k0 = s << 4;
        cp16(&As[s][soff],            Ar0 + k0);
        cp16(&As[s][soff + 64 * AST], Ar1 + k0);
        cp16(&Bs[s][soff],            Br0 + k0);
        cp16(&Bs[s][soff + 64 * AST], Br1 + k0);
        CP_COMMIT();
    }

    for (int kt = 0; kt < nk; kt++) {
        CP_WAIT(NSTAGE - 2);
        __syncthreads();

        if (kt + NSTAGE - 1 < nk) {
            const int buf = (kt + NSTAGE - 1) & (NSTAGE - 1);
            const int k0 = (kt + NSTAGE - 1) << 4;
            cp16(&As[buf][soff],            Ar0 + k0);
            cp16(&As[buf][soff + 64 * AST], Ar1 + k0);
            cp16(&Bs[buf][soff],            Br0 + k0);
            cp16(&Bs[buf][soff + 64 * AST], Br1 + k0);
        }
        CP_COMMIT();

        const uint32_t* Ab = (const uint32_t*)As[kt & (NSTAGE - 1)];
        const uint32_t* Bb = (const uint32_t*)Bs[kt & (NSTAGE - 1)];
#pragma unroll
        for (int ks = 0; ks < 2; ks++) {
            const int k0 = ks * 8;
            uint32_t af[4][4], bf[4][2];
#pragma unroll
            for (int i = 0; i < 4; i++) {
                const int row = warp_m + i * 16 + g;
                af[i][0] = Ab[row * AST + k0 + tg];
                af[i][1] = Ab[(row + 8) * AST + k0 + tg];
                af[i][2] = Ab[row * AST + k0 + tg + 4];
                af[i][3] = Ab[(row + 8) * AST + k0 + tg + 4];
            }
#pragma unroll
            for (int j = 0; j < 4; j++) {
                const int col = warp_n + j * 8 + g;
                bf[j][0] = Bb[col * AST + k0 + tg];
                bf[j][1] = Bb[col * AST + k0 + tg + 4];
            }
#pragma unroll
            for (int i = 0; i < 4; i++)
#pragma unroll
                for (int j = 0; j < 4; j++)
                    mma_tf32(acc[i][j], af[i][0], af[i][1], af[i][2], af[i][3],
                             bf[j][0], bf[j][1]);
        }
        // no trailing barrier: next iteration's wait_group+syncthreads protects reuse
    }

#pragma unroll
    for (int j = 0; j < 4; j++) {
        const int col = bn + warp_n + j * 8 + tg * 2;
        const float bx = bias[col], by = bias[col + 1];
#pragma unroll
        for (int i = 0; i < 4; i++) {
            const int row0 = bm + warp_m + i * 16 + g;
            const int row1 = row0 + 8;
            float o00 = acc[i][j][0] + bx, o01 = acc[i][j][1] + by;
            float o10 = acc[i][j][2] + bx, o11 = acc[i][j][3] + by;
            if (do_relu) {
                o00 = fmaxf(o00, 0.f); o01 = fmaxf(o01, 0.f);
                o10 = fmaxf(o10, 0.f); o11 = fmaxf(o11, 0.f);
            }
            if (resid) {
                const float2 r0v = *(const float2*)(resid + (size_t)row0 * N + col);
                const float2 r1v = *(const float2*)(resid + (size_t)row1 * N + col);
                o00 += r0v.x; o01 += r0v.y; o10 += r1v.x; o11 += r1v.y;
            }
            *(float2*)(C + (size_t)row0 * N + col) = make_float2(o00, o01);
            *(float2*)(C + (size_t)row1 * N + col) = make_float2(o10, o11);
        }
    }
}

__global__ __launch_bounds__(256) void gemm_tf32(
    const float* __restrict__ A, const float* __restrict__ B,
    const float* __restrict__ bias, const float* __restrict__ resid,
    float* __restrict__ C, int N, int K, int do_relu)
{
    gemm_body(A, B, bias, resid, C, N, K, do_relu,
              blockIdx.y * 128, blockIdx.x * 128);
}

__global__ __launch_bounds__(256) void gemm_tf32_multi(
    const float* __restrict__ A,
    const float* __restrict__ W0, const float* __restrict__ W1, const float* __restrict__ W2,
    const float* __restrict__ b0, const float* __restrict__ b1, const float* __restrict__ b2,
    float* __restrict__ C0, float* __restrict__ C1, float* __restrict__ C2)
{
    const int wsel = blockIdx.x >> 3;
    const int bn = (blockIdx.x & 7) * 128;
    const float* B    = (wsel == 0) ? W0 : (wsel == 1) ? W1 : W2;
    const float* bias = (wsel == 0) ? b0 : (wsel == 1) ? b1 : b2;
    float* C          = (wsel == 0) ? C0 : (wsel == 1) ? C1 : C2;
    gemm_body(A, B, bias, nullptr, C, D_MODEL, D_MODEL, 0,
              blockIdx.y * 128, bn);
}

// ================= 256x128 TF32 GEMM (one-wave variant for N=1024 GEMMs) ======
__global__ __launch_bounds__(256, 1) void gemm_tf32_big(
    const float* __restrict__ A, const float* __restrict__ B,
    const float* __restrict__ bias, const float* __restrict__ resid,
    float* __restrict__ C, int N, int K, int do_relu)
{
    __shared__ float As[NSTAGE][256 * AST];
    __shared__ float Bs[NSTAGE][128 * AST];

    const int tid  = threadIdx.x;
    const int warp = tid >> 5;
    const int lane = tid & 31;
    const int g    = lane >> 2;
    const int tg   = lane & 3;
    const int warp_m = (warp & 3) * 64;
    const int warp_n = (warp >> 2) * 64;
    const int bm = blockIdx.y * 256;
    const int bn = blockIdx.x * 128;

    const int r0 = tid >> 2;
    const int c4 = tid & 3;
    const float* Ar0 = A + (size_t)(bm + r0)       * K + c4 * 4;
    const float* Ar1 = A + (size_t)(bm + r0 + 64)  * K + c4 * 4;
    const float* Ar2 = A + (size_t)(bm + r0 + 128) * K + c4 * 4;
    const float* Ar3 = A + (size_t)(bm + r0 + 192) * K + c4 * 4;
    const float* Br0 = B + (size_t)(bn + r0)       * K + c4 * 4;
    const float* Br1 = B + (size_t)(bn + r0 + 64)  * K + c4 * 4;
    const int soff = r0 * AST + c4 * 4;

    float acc[4][8][4];
#pragma unroll
    for (int i = 0; i < 4; i++)
#pragma unroll
        for (int j = 0; j < 8; j++)
#pragma unroll
            for (int c = 0; c < 4; c++) acc[i][j][c] = 0.f;

    const int nk = K >> 4;

#pragma unroll
    for (int s = 0; s < NSTAGE - 1; s++) {
        const int k0 = s << 4;
        cp16(&As[s][soff],             Ar0 + k0);
        cp16(&As[s][soff + 64 * AST],  Ar1 + k0);
        cp16(&As[s][soff + 128 * AST], Ar2 + k0);
        cp16(&As[s][soff + 192 * AST], Ar3 + k0);
        cp16(&Bs[s][soff],             Br0 + k0);
        cp16(&Bs[s][soff + 64 * AST],  Br1 + k0);
        CP_COMMIT();
    }

    for (int kt = 0; kt < nk; kt++) {
        CP_WAIT(NSTAGE - 2);
        __syncthreads();

        if (kt + NSTAGE - 1 < nk) {
            const int buf = (kt + NSTAGE - 1) & (NSTAGE - 1);
            const int k0 = (kt + NSTAGE - 1) << 4;
            cp16(&As[buf][soff],             Ar0 + k0);
            cp16(&As[buf][soff + 64 * AST],  Ar1 + k0);
            cp16(&As[buf][soff + 128 * AST], Ar2 + k0);
            cp16(&As[buf][soff + 192 * AST], Ar3 + k0);
            cp16(&Bs[buf][soff],             Br0 + k0);
            cp16(&Bs[buf][soff + 64 * AST],  Br1 + k0);
        }
        CP_COMMIT();

        const uint32_t* Ab = (const uint32_t*)As[kt & (NSTAGE - 1)];
        const uint32_t* Bb = (const uint32_t*)Bs[kt & (NSTAGE - 1)];
#pragma unroll
        for (int ks = 0; ks < 2; ks++) {
            const int k0 = ks * 8;
            uint32_t af[4][4], bf[8][2];
#pragma unroll
            for (int i = 0; i < 4; i++) {
                const int row = warp_m + i * 16 + g;
                af[i][0] = Ab[row * AST + k0 + tg];
                af[i][1] = Ab[(row + 8) * AST + k0 + tg];
                af[i][2] = Ab[row * AST + k0 + tg + 4];
                af[i][3] = Ab[(row + 8) * AST + k0 + tg + 4];
            }
#pragma unroll
            for (int j = 0; j < 8; j++) {
                const int col = warp_n + j * 8 + g;
                bf[j][0] = Bb[col * AST + k0 + tg];
                bf[j][1] = Bb[col * AST + k0 + tg + 4];
            }
#pragma unroll
            for (int i = 0; i < 4; i++)
#pragma unroll
                for (int j = 0; j < 8; j++)
                    mma_tf32(acc[i][j], af[i][0], af[i][1], af[i][2], af[i][3],
                             bf[j][0], bf[j][1]);
        }
        // no trailing barrier (see gemm_body)
    }

#pragma unroll
    for (int j = 0; j < 8; j++) {
        const int col = bn + warp_n + j * 8 + tg * 2;
        const float bx = bias[col], by = bias[col + 1];
#pragma unroll
        for (int i = 0; i < 4; i++) {
            const int row0 = bm + warp_m + i * 16 + g;
            const int row1 = row0 + 8;
            float o00 = acc[i][j][0] + bx, o01 = acc[i][j][1] + by;
            float o10 = acc[i][j][2] + bx, o11 = acc[i][j][3] + by;
            if (do_relu) {
                o00 = fmaxf(o00, 0.f); o01 = fmaxf(o01, 0.f);
                o10 = fmaxf(o10, 0.f); o11 = fmaxf(o11, 0.f);
            }
            if (resid) {
                const float2 r0v = *(const float2*)(resid + (size_t)row0 * N + col);
                const float2 r1v = *(const float2*)(resid + (size_t)row1 * N + col);
                o00 += r0v.x; o01 += r0v.y; o10 += r1v.x; o11 += r1v.y;
            }
            *(float2*)(C + (size_t)row0 * N + col) = make_float2(o00, o01);
            *(float2*)(C + (size_t)row1 * N + col) = make_float2(o10, o11);
        }
    }
}

// ===== Flash attention, Br=128 x Bc=64, 256 thr, cp.async 2-stage K/V,
//       shuffle-based P conversion, exp2-domain softmax, 2 CTAs/SM
#define QST 68   // 68 % 32 == 4 -> conflict-free a-frag loads
#define VST 72   // 72 % 32 == 8 -> conflict-free V b-frag loads
#define KSTAGE_U32 (64 * QST)
#define VSTAGE_U32 (64 * VST)
// layout: Qs[128*QST] | Ks[2][64*QST] | Vs[2][64*VST]
#define FA5_SMEM_U32 (128*QST + 2*KSTAGE_U32 + 2*VSTAGE_U32)
#define FA5_SMEM_BYTES (FA5_SMEM_U32 * 4)
#define QSCALE (0.125f * 1.4426950408889634f)   // 1/sqrt(64) * log2(e)

__global__ __launch_bounds__(256, 2) void flash_attn_mma(
    const float* __restrict__ Q, const float* __restrict__ Kg,
    const float* __restrict__ Vg, float* __restrict__ O,
    int Tq, int Tk, int causal)
{
    extern __shared__ uint32_t smu[];
    uint32_t* Qs = smu;
    uint32_t* Ks = smu + 128 * QST;
    uint32_t* Vs = Ks + 2 * KSTAGE_U32;

    const int tid  = threadIdx.x;
    const int w    = tid >> 5;
    const int lane = tid & 31;
    const int g    = lane >> 2;
    const int tg   = lane & 3;
    const int m0   = w * 16;
    const int qtile = causal ? ((int)gridDim.x - 1 - (int)blockIdx.x) : (int)blockIdx.x;
    const int qb   = qtile * 128;
    const int h    = blockIdx.y;
    const int bb   = blockIdx.z;

    // shuffle sources for accumulator->A-frag conversion (within the 4-lane quad)
    const int srcA = (lane & 28) | (tg >> 1);
    const int srcB = srcA + 2;
    const bool odd = (tg & 1) != 0;

    const float* Qbase = Q  + (size_t)bb * Tq * D_MODEL + h * DHEAD;
    const float* Kbase = Kg + (size_t)bb * Tk * D_MODEL + h * DHEAD;
    const float* Vbase = Vg + (size_t)bb * Tk * D_MODEL + h * DHEAD;

    const int ntiles = causal ? (2 * (qtile + 1)) : (Tk >> 6);

    // prologue: async-load K/V tile 0 into stage 0
    {
#pragma unroll
        for (int i = 0; i < 4; i++) {
            const int f = tid + i * 256;
            const int r = f >> 4, d4 = f & 15;
            cp16(&Ks[r * QST + d4 * 4], Kbase + (size_t)r * D_MODEL + d4 * 4);
            cp16(&Vs[r * VST + d4 * 4], Vbase + (size_t)r * D_MODEL + d4 * 4);
        }
        CP_COMMIT();
    }

    // load Q tile (128 rows), pre-scaled into exp2 domain
#pragma unroll
    for (int i = 0; i < 8; i++) {
        const int f = tid + i * 256;
        const int r = f >> 4, d4 = f & 15;
        float4 v = *(const float4*)(Qbase + (size_t)(qb + r) * D_MODEL + d4 * 4);
        uint4 u = make_uint4(__float_as_uint(v.x * QSCALE), __float_as_uint(v.y * QSCALE),
                             __float_as_uint(v.z * QSCALE), __float_as_uint(v.w * QSCALE));
        *(uint4*)&Qs[r * QST + d4 * 4] = u;
    }

    float o[8][4];
#pragma unroll
    for (int nt = 0; nt < 8; nt++)
#pragma unroll
        for (int c = 0; c < 4; c++) o[nt][c] = 0.f;
    float mrow0 = -INFINITY, mrow1 = -INFINITY;
    float lrow0 = 0.f, lrow1 = 0.f;

    for (int t = 0; t < ntiles; t++) {
        // prefetch tile t+1 into the other stage
        if (t + 1 < ntiles) {
            const int kb1 = (t + 1) * 64;
            uint32_t* Kn = Ks + ((t + 1) & 1) * KSTAGE_U32;
            uint32_t* Vn = Vs + ((t + 1) & 1) * VSTAGE_U32;
#pragma unroll
            for (int i = 0; i < 4; i++) {
                const int f = tid + i * 256;
                const int r = f >> 4, d4 = f & 15;
                cp16(&Kn[r * QST + d4 * 4], Kbase + (size_t)(kb1 + r) * D_MODEL + d4 * 4);
                cp16(&Vn[r * VST + d4 * 4], Vbase + (size_t)(kb1 + r) * D_MODEL + d4 * 4);
            }
        }
        CP_COMMIT();
        CP_WAIT(1);
        __syncthreads();

        const uint32_t* Kb = Ks + (t & 1) * KSTAGE_U32;
        const uint32_t* Vb = Vs + (t & 1) * VSTAGE_U32;
        const int kb = t * 64;

        // ---- S = Q @ K^T (16x64 per warp), S in log2-units ----
        float s[8][4];
#pragma unroll
        for (int nt = 0; nt < 8; nt++)
#pragma unroll
            for (int c = 0; c < 4; c++) s[nt][c] = 0.f;
#pragma unroll
        for (int kk = 0; kk < 8; kk++) {
            const int k0 = kk * 8;
            const uint32_t a0 = Qs[(m0 + g)     * QST + k0 + tg];
            const uint32_t a1 = Qs[(m0 + g + 8) * QST + k0 + tg];
            const uint32_t a2 = Qs[(m0 + g)     * QST + k0 + tg + 4];
            const uint32_t a3 = Qs[(m0 + g + 8) * QST + k0 + tg + 4];
#pragma unroll
            for (int nt = 0; nt < 8; nt++) {
                const uint32_t b0 = Kb[(nt * 8 + g) * QST + k0 + tg];
                const uint32_t b1 = Kb[(nt * 8 + g) * QST + k0 + tg + 4];
                mma_tf32(s[nt], a0, a1, a2, a3, b0, b1);
            }
        }

        if (causal && t >= 2 * qtile) {
            const int row0 = qb + m0 + g;
            const int row1 = row0 + 8;
#pragma unroll
            for (int nt = 0; nt < 8; nt++) {
                const int col = kb + nt * 8 + 2 * tg;
                if (col     > row0) s[nt][0] = -1e30f;
                if (col + 1 > row0) s[nt][1] = -1e30f;
                if (col     > row1) s[nt][2] = -1e30f;
                if (col + 1 > row1) s[nt][3] = -1e30f;
            }
        }

        // ---- online softmax in exp2 domain ----
        float ml0 = -INFINITY, ml1 = -INFINITY;
#pragma unroll
        for (int nt = 0; nt < 8; nt++) {
            ml0 = fmaxf(ml0, fmaxf(s[nt][0], s[nt][1]));
            ml1 = fmaxf(ml1, fmaxf(s[nt][2], s[nt][3]));
        }
        ml0 = fmaxf(ml0, __shfl_xor_sync(0xffffffffu, ml0, 1));
        ml0 = fmaxf(ml0, __shfl_xor_sync(0xffffffffu, ml0, 2));
        ml1 = fmaxf(ml1, __shfl_xor_sync(0xffffffffu, ml1, 1));
        ml1 = fmaxf(ml1, __shfl_xor_sync(0xffffffffu, ml1, 2));

        const float mn0 = fmaxf(mrow0, ml0);
        const float mn1 = fmaxf(mrow1, ml1);
        const float al0 = fast_exp2(mrow0 - mn0);
        const float al1 = fast_exp2(mrow1 - mn1);
        float ps0 = 0.f, ps1 = 0.f;
#pragma unroll
        for (int nt = 0; nt < 8; nt++) {
            s[nt][0] = fast_exp2(s[nt][0] - mn0);
            s[nt][1] = fast_exp2(s[nt][1] - mn0);
            s[nt][2] = fast_exp2(s[nt][2] - mn1);
            s[nt][3] = fast_exp2(s[nt][3] - mn1);
            ps0 += s[nt][0] + s[nt][1];
            ps1 += s[nt][2] + s[nt][3];
        }
        ps0 += __shfl_xor_sync(0xffffffffu, ps0, 1);
        ps0 += __shfl_xor_sync(0xffffffffu, ps0, 2);
        ps1 += __shfl_xor_sync(0xffffffffu, ps1, 1);
        ps1 += __shfl_xor_sync(0xffffffffu, ps1, 2);
        lrow0 = lrow0 * al0 + ps0;
        lrow1 = lrow1 * al1 + ps1;
        mrow0 = mn0;
        mrow1 = mn1;
#pragma unroll
        for (int nt = 0; nt < 8; nt++) {
            o[nt][0] *= al0; o[nt][1] *= al0;
            o[nt][2] *= al1; o[nt][3] *= al1;
        }

        // ---- O += P @ V : shuffle-convert accumulator frags -> A frags ----
#pragma unroll
        for (int kk = 0; kk < 8; kk++) {
            const float v0 = __shfl_sync(0xffffffffu, s[kk][0], srcA);
            const float v1 = __shfl_sync(0xffffffffu, s[kk][1], srcA);
            const float v2 = __shfl_sync(0xffffffffu, s[kk][2], srcA);
            const float v3 = __shfl_sync(0xffffffffu, s[kk][3], srcA);
            const float w0 = __shfl_sync(0xffffffffu, s[kk][0], srcB);
            const float w1 = __shfl_sync(0xffffffffu, s[kk][1], srcB);
            const float w2 = __shfl_sync(0xffffffffu, s[kk][2], srcB);
            const float w3 = __shfl_sync(0xffffffffu, s[kk][3], srcB);
            const uint32_t a0 = __float_as_uint(odd ? v1 : v0);
            const uint32_t a1 = __float_as_uint(odd ? v3 : v2);
            const uint32_t a2 = __float_as_uint(odd ? w1 : w0);
            const uint32_t a3 = __float_as_uint(odd ? w3 : w2);
            const int k0 = kk * 8;
#pragma unroll
            for (int nt = 0; nt < 8; nt++) {
                const uint32_t b0 = Vb[(k0 + tg)     * VST + nt * 8 + g];
                const uint32_t b1 = Vb[(k0 + tg + 4) * VST + nt * 8 + g];
                mma_tf32(o[nt], a0, a1, a2, a3, b0, b1);
            }
        }
        __syncthreads();   // all reads of stage (t&1) done before its reuse at t+2
    }

    const float inv0 = 1.f / lrow0;
    const float inv1 = 1.f / lrow1;
    const int row0 = qb + m0 + g;
    const int row1 = row0 + 8;
#pragma unroll
    for (int nt = 0; nt < 8; nt++) {
        const int col = h * DHEAD + nt * 8 + 2 * tg;
        *(float2*)(O + ((size_t)bb * Tq + row0) * D_MODEL + col) =
            make_float2(o[nt][0] * inv0, o[nt][1] * inv0);
        *(float2*)(O + ((size_t)bb * Tq + row1) * D_MODEL + col) =
            make_float2(o[nt][2] * inv1, o[nt][3] * inv1);
    }
}

// ---------------- LN over rows of 1024 ----------------
__global__ __launch_bounds__(256) void ln_kernel(
    const float* __restrict__ in, const float* __restrict__ g,
    const float* __restrict__ b, float* __restrict__ out)
{
    const int row = blockIdx.x;
    const int tid = threadIdx.x;
    float4 v = ((const float4*)(in + (size_t)row * D_MODEL))[tid];
    float s  = v.x + v.y + v.z + v.w;
    float ss = v.x*v.x + v.y*v.y + v.z*v.z + v.w*v.w;
#pragma unroll
    for (int off = 16; off > 0; off >>= 1) {
        s  += __shfl_xor_sync(0xffffffffu, s,  off);
        ss += __shfl_xor_sync(0xffffffffu, ss, off);
    }
    __shared__ float ws[8], wss[8];
    __shared__ float s_mu, s_inv;
    const int warp = tid >> 5, lane = tid & 31;
    if (lane == 0) { ws[warp] = s; wss[warp] = ss; }
    __syncthreads();
    if (tid == 0) {
        float ts = 0.f, tss = 0.f;
#pragma unroll
        for (int w = 0; w < 8; w++) { ts += ws[w]; tss += wss[w]; }
        float mu = ts * (1.f / D_MODEL);
        float var = tss * (1.f / D_MODEL) - mu * mu;
        s_mu = mu;
        s_inv = rsqrtf(var + 1e-5f);
    }
    __syncthreads();
    float mu = s_mu, inv = s_inv;
    float4 gg = ((const float4*)g)[tid];
    float4 bb = ((const float4*)b)[tid];
    float4 r;
    r.x = (v.x - mu) * inv * gg.x + bb.x;
    r.y = (v.y - mu) * inv * gg.y + bb.y;
    r.z = (v.z - mu) * inv * gg.z + bb.z;
    r.w = (v.w - mu) * inv * gg.w + bb.w;
    ((float4*)(out + (size_t)row * D_MODEL))[tid] = r;
}

// ---------------- orchestration ----------------
extern "C" void kernel_launch(void* const* d_in, const int* in_sizes, int n_in,
                              void* d_out, int out_size)
{
    const float* x     = (const float*)d_in[0];
    const float* enc   = (const float*)d_in[1];
    const float* sa_Wq = (const float*)d_in[4];
    const float* sa_bq = (const float*)d_in[5];
    const float* sa_Wk = (const float*)d_in[6];
    const float* sa_bk = (const float*)d_in[7];
    const float* sa_Wv = (const float*)d_in[8];
    const float* sa_bv = (const float*)d_in[9];
    const float* sa_Wo = (const float*)d_in[10];
    const float* sa_bo = (const float*)d_in[11];
    const float* ca_Wq = (const float*)d_in[12];
    const float* ca_bq = (const float*)d_in[13];
    const float* ca_Wk = (const float*)d_in[14];
    const float* ca_bk = (const float*)d_in[15];
    const float* ca_Wv = (const float*)d_in[16];
    const float* ca_bv = (const float*)d_in[17];
    const float* ca_Wo = (const float*)d_in[18];
    const float* ca_bo = (const float*)d_in[19];
    const float* ff_W1 = (const float*)d_in[20];
    const float* ff_b1 = (const float*)d_in[21];
    const float* ff_W2 = (const float*)d_in[22];
    const float* ff_b2 = (const float*)d_in[23];
    const float* ln1_g = (const float*)d_in[24];
    const float* ln1_b = (const float*)d_in[25];
    const float* ln2_g = (const float*)d_in[26];
    const float* ln2_b = (const float*)d_in[27];
    const float* ln3_g = (const float*)d_in[28];
    const float* ln3_b = (const float*)d_in[29];

    float *q, *k, *v, *ctx, *tmp, *x1, *x2, *ffh;
    cudaGetSymbolAddress((void**)&q,   g_q);
    cudaGetSymbolAddress((void**)&k,   g_k);
    cudaGetSymbolAddress((void**)&v,   g_v);
    cudaGetSymbolAddress((void**)&ctx, g_ctx);
    cudaGetSymbolAddress((void**)&tmp, g_tmp);
    cudaGetSymbolAddress((void**)&x1,  g_x1);
    cudaGetSymbolAddress((void**)&x2,  g_x2);
    cudaGetSymbolAddress((void**)&ffh, g_ffh);

    cudaFuncSetAttribute(flash_attn_mma, cudaFuncAttributeMaxDynamicSharedMemorySize, FA5_SMEM_BYTES);

    dim3 gqkv(24, MROWS/128);               // fused q,k,v projections (128-tile)
    dim3 gkv2(16, MROWS/128);               // fused cross k,v (128-tile)
    dim3 gbig(D_MODEL/128, MROWS/256);      // (8,16) = 128 blocks, one wave
    dim3 gf1(DFF_/128,  MROWS/128);         // FFN up
    dim3 gfa(TT/128, NHEAD, BB);            // flash attention (Br=128)

    // --- self attention ---
    gemm_tf32_multi<<<gqkv, 256>>>(x, sa_Wq, sa_Wk, sa_Wv, sa_bq, sa_bk, sa_bv, q, k, v);
    flash_attn_mma<<<gfa, 256, FA5_SMEM_BYTES>>>(q, k, v, ctx, TT, TT, 1);
    gemm_tf32_big<<<gbig, 256>>>(ctx, sa_Wo, sa_bo, x, tmp, D_MODEL, D_MODEL, 0);
    ln_kernel<<<MROWS, 256>>>(tmp, ln1_g, ln1_b, x1);

    // --- cross attention ---
    gemm_tf32_multi<<<gkv2, 256>>>(enc, ca_Wk, ca_Wv, nullptr, ca_bk, ca_bv, nullptr, k, v, nullptr);
    gemm_tf32_big<<<gbig, 256>>>(x1, ca_Wq, ca_bq, nullptr, q, D_MODEL, D_MODEL, 0);
    flash_attn_mma<<<gfa, 256, FA5_SMEM_BYTES>>>(q, k, v, ctx, TT, SSEQ, 0);
    gemm_tf32_big<<<gbig, 256>>>(ctx, ca_Wo, ca_bo, x1, tmp, D_MODEL, D_MODEL, 0);
    ln_kernel<<<MROWS, 256>>>(tmp, ln2_g, ln2_b, x2);

    // --- FFN ---
    gemm_tf32<<<gf1, 256>>>(x2,  ff_W1, ff_b1, nullptr, ffh, DFF_,    D_MODEL, 1);
    gemm_tf32_big<<<gbig, 256>>>(ffh, ff_W2, ff_b2, x2,  tmp, D_MODEL, DFF_,    0);
    ln_kernel<<<MROWS, 256>>>(tmp, ln3_g, ln3_b, (float*)d_out);
}